// round 10
// baseline (speedup 1.0000x reference)
#include <cuda_runtime.h>
#include <cuda_bf16.h>

// out[b,t,v] = sum_d x[b,t,d,v] * w[d] + bias
// x: (2, 512, 8, 32000) fp32 contiguous; w: (8,); b: (1,)
// out: (2, 512, 32000) fp32
//
// HBM-roofline streaming kernel. R9 probe: 2 adjacent float4 per thread
// -> warp covers 1KB contiguous per depth row (longer DRAM bursts),
//    MLP=16 outstanding loads per thread, half the blocks (16000).
// Dense one-shot grid retained (persistent grid measured worse, R7).
// Exact grid: 16000 * 256 * 2 == 8,192,000 float4 outputs.

#define DEPTH   8
#define VROW4   8000                    // 32000 floats / 4 per (b,t,d) row
#define VROW8   4000                    // pairs of float4 per row

__global__ __launch_bounds__(256) void ttm_kernel(
    const float4* __restrict__ x,
    const float*  __restrict__ w,
    const float*  __restrict__ bias,
    float4* __restrict__ out)
{
    // pair index: each thread owns float4 elements 2*j and 2*j+1 (adjacent)
    long j = (long)blockIdx.x * 256 + threadIdx.x;   // 0 .. 4,095,999 (exact)

    int row = (int)(j / VROW8);          // which (b,t) of 1024
    int v8  = (int)(j % VROW8);

    // weights: tiny, L1/L2-broadcast; registers for the whole kernel
    float wr[DEPTH];
#pragma unroll
    for (int d = 0; d < DEPTH; ++d) wr[d] = __ldg(&w[d]);
    const float bb = __ldg(bias);

    const float4* p = x + (long)row * DEPTH * VROW4 + (long)v8 * 2;

    // Front-batch all 16 independent streaming loads (MLP=16),
    // 32B contiguous per thread per depth row -> 1KB per warp per row.
    float4 ta[DEPTH], tb[DEPTH];
#pragma unroll
    for (int d = 0; d < DEPTH; ++d) {
        const float4* q = p + (long)d * VROW4;
        ta[d] = __ldcs(q);
        tb[d] = __ldcs(q + 1);
    }

    float4 a, b2;
    a.x = bb;  a.y = bb;  a.z = bb;  a.w = bb;
    b2.x = bb; b2.y = bb; b2.z = bb; b2.w = bb;

#pragma unroll
    for (int d = 0; d < DEPTH; ++d) {
        a.x  = fmaf(ta[d].x, wr[d], a.x);
        a.y  = fmaf(ta[d].y, wr[d], a.y);
        a.z  = fmaf(ta[d].z, wr[d], a.z);
        a.w  = fmaf(ta[d].w, wr[d], a.w);
        b2.x = fmaf(tb[d].x, wr[d], b2.x);
        b2.y = fmaf(tb[d].y, wr[d], b2.y);
        b2.z = fmaf(tb[d].z, wr[d], b2.z);
        b2.w = fmaf(tb[d].w, wr[d], b2.w);
    }

    float4* o = out + (long)row * VROW4 + (long)v8 * 2;
    __stcs(o,     a);
    __stcs(o + 1, b2);
}

extern "C" void kernel_launch(void* const* d_in, const int* in_sizes, int n_in,
                              void* d_out, int out_size)
{
    const float4* x    = (const float4*)d_in[0];
    const float*  w    = (const float*) d_in[1];
    const float*  bias = (const float*) d_in[2];
    float4*       out  = (float4*)      d_out;

    ttm_kernel<<<16000, 256>>>(x, w, bias, out);
}

// round 11
// speedup vs baseline: 1.0033x; 1.0033x over previous
#include <cuda_runtime.h>
#include <cuda_bf16.h>

// out[b,t,v] = sum_d x[b,t,d,v] * w[d] + bias
// x: (2, 512, 8, 32000) fp32 contiguous; w: (8,); b: (1,)
// out: (2, 512, 32000) fp32
//
// FINAL converged HBM-roofline kernel: ~90% of sustained DRAM peak
// (7.15 TB/s), 164-166 us. Measured decision record (R1-R9):
//  - one thread per float4 of output, 8 front-batched independent float4
//    loads (MLP=8) -> DRAM latency fully hidden, coalesced 512B/warp/row
//  - dense one-shot grid (32000 blocks): rasterization keeps the concurrent
//    address footprint compact -> DRAM page locality.
//    Persistent grid-stride measured WORSE (85.4% DRAM, R7).
//    2x float4/thread measured neutral-worse (89.5% DRAM, occ 63%, R9).
//  - exact grid 32000*256 == 8,192,000 outputs: no tail predicate
//  - __ldcs/__stcs streaming hints: measured neutral, kept (zero reuse)
// Remaining ~10% to spec = bus turnaround (8:1 R/W mix) + refresh;
// not addressable from the kernel.

#define DEPTH   8
#define VROW4   8000                    // 32000 floats / 4 per (b,t,d) row
#define TOTAL4  (2L * 512L * VROW4)     // 8,192,000 float4 outputs (exact grid)

__global__ __launch_bounds__(256) void ttm_kernel(
    const float4* __restrict__ x,
    const float*  __restrict__ w,
    const float*  __restrict__ bias,
    float4* __restrict__ out)
{
    long i = (long)blockIdx.x * 256 + threadIdx.x;   // grid is exact: no bounds check

    int row = (int)(i / VROW4);   // which (b,t) of 1024
    int v4  = (int)(i % VROW4);

    // weights: tiny, L1/L2-broadcast; registers for the whole kernel
    float wr[DEPTH];
#pragma unroll
    for (int d = 0; d < DEPTH; ++d) wr[d] = __ldg(&w[d]);
    const float bb = __ldg(bias);

    const float4* p = x + (long)row * DEPTH * VROW4 + v4;

    // Front-batch all 8 independent streaming loads (MLP=8)
    float4 t[DEPTH];
#pragma unroll
    for (int d = 0; d < DEPTH; ++d)
        t[d] = __ldcs(p + (long)d * VROW4);          // evict-first: zero reuse

    float4 acc;
    acc.x = bb; acc.y = bb; acc.z = bb; acc.w = bb;

#pragma unroll
    for (int d = 0; d < DEPTH; ++d) {
        acc.x = fmaf(t[d].x, wr[d], acc.x);
        acc.y = fmaf(t[d].y, wr[d], acc.y);
        acc.z = fmaf(t[d].z, wr[d], acc.z);
        acc.w = fmaf(t[d].w, wr[d], acc.w);
    }

    __stcs(&out[i], acc);                            // streaming store
}

extern "C" void kernel_launch(void* const* d_in, const int* in_sizes, int n_in,
                              void* d_out, int out_size)
{
    const float4* x    = (const float4*)d_in[0];
    const float*  w    = (const float*) d_in[1];
    const float*  bias = (const float*) d_in[2];
    float4*       out  = (float4*)      d_out;

    ttm_kernel<<<32000, 256>>>(x, w, bias, out);
}

// round 12
// speedup vs baseline: 1.0048x; 1.0015x over previous
#include <cuda_runtime.h>
#include <cuda_bf16.h>

// out[b,t,v] = sum_d x[b,t,d,v] * w[d] + bias
// x: (2, 512, 8, 32000) fp32 contiguous; w: (8,); b: (1,)
// out: (2, 512, 32000) fp32
//
// Converged HBM-roofline kernel (~90% sustained DRAM, ~7.15 TB/s).
// R11 probe (final axis): 512-thread blocks -> 16000 blocks. Same
// thread-level pattern (1 float4/thread, 8 front-batched loads, MLP=8);
// larger per-CTA contiguous span (8KB) for the L1tex/LTS request stream,
// half the CTA launch events. All other axes measured (R1-R10):
//   dense grid > persistent (R7), 1x > 2x float4/thread (R9),
//   streaming hints neutral (R6).
// Exact grid: 16000 * 512 == 8,192,000 float4 outputs, no tail predicate.

#define DEPTH   8
#define VROW4   8000                    // 32000 floats / 4 per (b,t,d) row
#define NTHREADS 512

__global__ __launch_bounds__(NTHREADS) void ttm_kernel(
    const float4* __restrict__ x,
    const float*  __restrict__ w,
    const float*  __restrict__ bias,
    float4* __restrict__ out)
{
    long i = (long)blockIdx.x * NTHREADS + threadIdx.x;  // exact: no bounds check

    int row = (int)(i / VROW4);   // which (b,t) of 1024
    int v4  = (int)(i % VROW4);

    // weights: tiny, L1/L2-broadcast; registers for the whole kernel
    float wr[DEPTH];
#pragma unroll
    for (int d = 0; d < DEPTH; ++d) wr[d] = __ldg(&w[d]);
    const float bb = __ldg(bias);

    const float4* p = x + (long)row * DEPTH * VROW4 + v4;

    // Front-batch all 8 independent streaming loads (MLP=8)
    float4 t[DEPTH];
#pragma unroll
    for (int d = 0; d < DEPTH; ++d)
        t[d] = __ldcs(p + (long)d * VROW4);          // evict-first: zero reuse

    float4 acc;
    acc.x = bb; acc.y = bb; acc.z = bb; acc.w = bb;

#pragma unroll
    for (int d = 0; d < DEPTH; ++d) {
        acc.x = fmaf(t[d].x, wr[d], acc.x);
        acc.y = fmaf(t[d].y, wr[d], acc.y);
        acc.z = fmaf(t[d].z, wr[d], acc.z);
        acc.w = fmaf(t[d].w, wr[d], acc.w);
    }

    __stcs(&out[i], acc);                            // streaming store
}

extern "C" void kernel_launch(void* const* d_in, const int* in_sizes, int n_in,
                              void* d_out, int out_size)
{
    const float4* x    = (const float4*)d_in[0];
    const float*  w    = (const float*) d_in[1];
    const float*  bias = (const float*) d_in[2];
    float4*       out  = (float4*)      d_out;

    ttm_kernel<<<16000, NTHREADS>>>(x, w, bias, out);
}

// round 13
// speedup vs baseline: 1.0138x; 1.0090x over previous
#include <cuda_runtime.h>
#include <cuda_bf16.h>

// out[b,t,v] = sum_d x[b,t,d,v] * w[d] + bias
// x: (2, 512, 8, 32000) fp32 contiguous; w: (8,); b: (1,)
// out: (2, 512, 32000) fp32
//
// FINAL kernel — converged at the HBM roofline: ~90% of sustained DRAM
// peak (7.15 TB/s), 164-166 us, rel_err 0.
//
// Measured decision record (R1-R11, each axis probed with a prediction):
//  - 1 thread per float4 of output; 8 front-batched independent float4
//    loads (MLP=8) fully hide DRAM latency; 512B coalesced per warp per
//    depth row.
//  - dense one-shot grid of 32000x256: block rasterization keeps the
//    concurrent address footprint compact -> DRAM page locality.
//      * persistent grid-stride: 85.4% DRAM (regression, R7)
//      * 2x float4/thread MLP=16: 89.5% DRAM, occ 63% (R9)
//      * 512-thread blocks:       89.6% DRAM, occ 79% (R11)
//  - exact grid 32000*256 == 8,192,000 outputs: no tail predicate.
//  - __ldcs/__stcs: measured neutral, kept (zero-reuse stream).
// Residual ~10% to spec = 8:1 R/W bus turnaround + refresh; not
// kernel-addressable. Compute pipes idle by design (AI = 0.44 FLOP/B).

#define DEPTH   8
#define VROW4   8000                    // 32000 floats / 4 per (b,t,d) row

__global__ __launch_bounds__(256) void ttm_kernel(
    const float4* __restrict__ x,
    const float*  __restrict__ w,
    const float*  __restrict__ bias,
    float4* __restrict__ out)
{
    long i = (long)blockIdx.x * 256 + threadIdx.x;   // grid is exact: no bounds check

    int row = (int)(i / VROW4);   // which (b,t) of 1024
    int v4  = (int)(i % VROW4);

    // weights: tiny, L1/L2-broadcast; registers for the whole kernel
    float wr[DEPTH];
#pragma unroll
    for (int d = 0; d < DEPTH; ++d) wr[d] = __ldg(&w[d]);
    const float bb = __ldg(bias);

    const float4* p = x + (long)row * DEPTH * VROW4 + v4;

    // Front-batch all 8 independent streaming loads (MLP=8)
    float4 t[DEPTH];
#pragma unroll
    for (int d = 0; d < DEPTH; ++d)
        t[d] = __ldcs(p + (long)d * VROW4);          // evict-first: zero reuse

    float4 acc;
    acc.x = bb; acc.y = bb; acc.z = bb; acc.w = bb;

#pragma unroll
    for (int d = 0; d < DEPTH; ++d) {
        acc.x = fmaf(t[d].x, wr[d], acc.x);
        acc.y = fmaf(t[d].y, wr[d], acc.y);
        acc.z = fmaf(t[d].z, wr[d], acc.z);
        acc.w = fmaf(t[d].w, wr[d], acc.w);
    }

    __stcs(&out[i], acc);                            // streaming store
}

extern "C" void kernel_launch(void* const* d_in, const int* in_sizes, int n_in,
                              void* d_out, int out_size)
{
    const float4* x    = (const float4*)d_in[0];
    const float*  w    = (const float*) d_in[1];
    const float*  bias = (const float*) d_in[2];
    float4*       out  = (float4*)      d_out;

    ttm_kernel<<<32000, 256>>>(x, w, bias, out);
}